// round 2
// baseline (speedup 1.0000x reference)
#include <cuda_runtime.h>
#include <cuda_bf16.h>

// Problem shapes (fixed by the dataset)
#define BATCH 8
#define MDIM 2048
#define LDIM 2048
#define HDIM 1024

// Tile config
#define BM 128
#define BN 128
#define BK 8
#define TM 8
#define TN 8
#define NTHREADS 256

// Scratch: T[b] = K[b]^T @ V[b], shape [B, H, H] fp32 = 32 MB.
// __device__ global is the sanctioned scratch mechanism (no allocs allowed).
__device__ float g_T[(size_t)BATCH * HDIM * HDIM];

// ---------------------------------------------------------------------------
// Kernel 1: T[b][i][j] = sum_l K[b][l][i] * V[b][l][j]   (A^T * B form)
// A = K [L,H] row-major: A^T tile loads are contiguous in i -> no smem transpose.
// ---------------------------------------------------------------------------
__global__ __launch_bounds__(NTHREADS, 2) void ktv_kernel(
    const float* __restrict__ Kp, const float* __restrict__ Vp)
{
    const int b = blockIdx.z;
    const float* A = Kp + (size_t)b * LDIM * HDIM;  // [L,H]
    const float* B = Vp + (size_t)b * LDIM * HDIM;  // [L,H]
    float* C = g_T + (size_t)b * HDIM * HDIM;       // [H,H]

    __shared__ float As[BK][BM];
    __shared__ float Bs[BK][BN];

    const int row0 = blockIdx.y * BM;  // i
    const int col0 = blockIdx.x * BN;  // j
    const int tid = threadIdx.x;

    // Global->shared: 256 threads, each one float4 per tile (BK*BM = 1024 floats)
    const int ak = tid >> 5;            // 0..7
    const int am = (tid & 31) << 2;     // 0..124 step 4

    const int ty = tid >> 4;            // 0..15
    const int tx = tid & 15;            // 0..15

    float acc[TM][TN];
#pragma unroll
    for (int i = 0; i < TM; i++)
#pragma unroll
        for (int j = 0; j < TN; j++) acc[i][j] = 0.0f;

    for (int l0 = 0; l0 < LDIM; l0 += BK) {
        // As[k][m] = K[(l0+k)][row0+m]  (contiguous in m)
        *(float4*)&As[ak][am] =
            *(const float4*)&A[(size_t)(l0 + ak) * HDIM + row0 + am];
        // Bs[k][n] = V[(l0+k)][col0+n]
        *(float4*)&Bs[ak][am] =
            *(const float4*)&B[(size_t)(l0 + ak) * HDIM + col0 + am];
        __syncthreads();

#pragma unroll
        for (int k = 0; k < BK; k++) {
            float ar[TM], br[TN];
            const float4* a4 = (const float4*)&As[k][ty * TM];
            float4 a_lo = a4[0], a_hi = a4[1];
            ar[0] = a_lo.x; ar[1] = a_lo.y; ar[2] = a_lo.z; ar[3] = a_lo.w;
            ar[4] = a_hi.x; ar[5] = a_hi.y; ar[6] = a_hi.z; ar[7] = a_hi.w;
            const float4* b4 = (const float4*)&Bs[k][tx * TN];
            float4 b_lo = b4[0], b_hi = b4[1];
            br[0] = b_lo.x; br[1] = b_lo.y; br[2] = b_lo.z; br[3] = b_lo.w;
            br[4] = b_hi.x; br[5] = b_hi.y; br[6] = b_hi.z; br[7] = b_hi.w;
#pragma unroll
            for (int i = 0; i < TM; i++)
#pragma unroll
                for (int j = 0; j < TN; j++)
                    acc[i][j] = fmaf(ar[i], br[j], acc[i][j]);
        }
        __syncthreads();
    }

#pragma unroll
    for (int i = 0; i < TM; i++) {
        const int r = row0 + ty * TM + i;
        float* crow = &C[(size_t)r * HDIM + col0 + tx * TN];
        float4 v0 = make_float4(acc[i][0], acc[i][1], acc[i][2], acc[i][3]);
        float4 v1 = make_float4(acc[i][4], acc[i][5], acc[i][6], acc[i][7]);
        *(float4*)&crow[0] = v0;
        *(float4*)&crow[4] = v1;
    }
}

// ---------------------------------------------------------------------------
// Kernel 2: O[b][m][j] = sum_h Q[b][m][h] * T[b][h][j]   (A * B form)
// A = Q [M,H] row-major: transpose-on-store into As.
// ---------------------------------------------------------------------------
__global__ __launch_bounds__(NTHREADS, 2) void qt_kernel(
    const float* __restrict__ Qp, float* __restrict__ Op)
{
    const int b = blockIdx.z;
    const float* A = Qp + (size_t)b * MDIM * HDIM;      // [M,H]
    const float* B = g_T + (size_t)b * HDIM * HDIM;     // [H,H]
    float* C = Op + (size_t)b * MDIM * HDIM;            // [M,H]

    __shared__ float As[BK][BM];
    __shared__ float Bs[BK][BN];

    const int row0 = blockIdx.y * BM;  // m
    const int col0 = blockIdx.x * BN;  // j
    const int tid = threadIdx.x;

    // A tile: BM x BK = 128 x 8 = 256 float4 (one per thread), transposed store
    const int am = tid >> 1;            // 0..127
    const int akk = (tid & 1) << 2;     // 0 or 4

    // B tile: BK x BN direct
    const int bk = tid >> 5;
    const int bn = (tid & 31) << 2;

    const int ty = tid >> 4;
    const int tx = tid & 15;

    float acc[TM][TN];
#pragma unroll
    for (int i = 0; i < TM; i++)
#pragma unroll
        for (int j = 0; j < TN; j++) acc[i][j] = 0.0f;

    for (int h0 = 0; h0 < HDIM; h0 += BK) {
        float4 av = *(const float4*)&A[(size_t)(row0 + am) * HDIM + h0 + akk];
        As[akk + 0][am] = av.x;
        As[akk + 1][am] = av.y;
        As[akk + 2][am] = av.z;
        As[akk + 3][am] = av.w;
        *(float4*)&Bs[bk][bn] =
            *(const float4*)&B[(size_t)(h0 + bk) * HDIM + col0 + bn];
        __syncthreads();

#pragma unroll
        for (int k = 0; k < BK; k++) {
            float ar[TM], br[TN];
            const float4* a4 = (const float4*)&As[k][ty * TM];
            float4 a_lo = a4[0], a_hi = a4[1];
            ar[0] = a_lo.x; ar[1] = a_lo.y; ar[2] = a_lo.z; ar[3] = a_lo.w;
            ar[4] = a_hi.x; ar[5] = a_hi.y; ar[6] = a_hi.z; ar[7] = a_hi.w;
            const float4* b4 = (const float4*)&Bs[k][tx * TN];
            float4 b_lo = b4[0], b_hi = b4[1];
            br[0] = b_lo.x; br[1] = b_lo.y; br[2] = b_lo.z; br[3] = b_lo.w;
            br[4] = b_hi.x; br[5] = b_hi.y; br[6] = b_hi.z; br[7] = b_hi.w;
#pragma unroll
            for (int i = 0; i < TM; i++)
#pragma unroll
                for (int j = 0; j < TN; j++)
                    acc[i][j] = fmaf(ar[i], br[j], acc[i][j]);
        }
        __syncthreads();
    }

#pragma unroll
    for (int i = 0; i < TM; i++) {
        const int r = row0 + ty * TM + i;
        float* crow = &C[(size_t)r * HDIM + col0 + tx * TN];
        float4 v0 = make_float4(acc[i][0], acc[i][1], acc[i][2], acc[i][3]);
        float4 v1 = make_float4(acc[i][4], acc[i][5], acc[i][6], acc[i][7]);
        *(float4*)&crow[0] = v0;
        *(float4*)&crow[4] = v1;
    }
}

// ---------------------------------------------------------------------------
// Launch: out = Q @ (K^T @ V)  per batch. key_pe / hidden_size are dead
// inputs (attn_pos and the softmax are dead code in the reference).
// ---------------------------------------------------------------------------
extern "C" void kernel_launch(void* const* d_in, const int* in_sizes, int n_in,
                              void* d_out, int out_size)
{
    const float* q = (const float*)d_in[0];  // [B, M, H]
    const float* k = (const float*)d_in[1];  // [B, L, H]
    const float* v = (const float*)d_in[2];  // [B, L, H]
    float* out = (float*)d_out;              // [B, M, H]

    // Stage 1: T[b] = K[b]^T @ V[b]   -> grid (H/BN, H/BM, B)
    dim3 grid1(HDIM / BN, HDIM / BM, BATCH);
    ktv_kernel<<<grid1, NTHREADS>>>(k, v);

    // Stage 2: O[b] = Q[b] @ T[b]     -> grid (H/BN, M/BM, B)
    dim3 grid2(HDIM / BN, MDIM / BM, BATCH);
    qt_kernel<<<grid2, NTHREADS>>>(q, out);
}